// round 6
// baseline (speedup 1.0000x reference)
#include <cuda_runtime.h>
#include <cuda_bf16.h>

// Problem constants
#define BATCH   32
#define CIN     128
#define COUT    256
#define Hh      56
#define Ww      56
#define KEXP    8
#define HIDDEN  32
#define HW      (Hh * Ww)          // 3136

// Conv tiling
#define KC      8                  // cin chunk
#define OCB     64                 // oc per block
#define TS      8                  // 8x8 spatial tile

// ---------------- scratch (static device globals; no runtime alloc) -------
__device__ float g_v[BATCH * CIN];                    // GAP result
__device__ float g_alpha[BATCH * KEXP];               // routing weights
// Dynamic weights, TRANSPOSED layout: [b][c][ij][oc]  (oc fastest)
__device__ float g_wdyn[BATCH * CIN * 9 * COUT];      // 37.7 MB

// ---------------- packed-pair helpers -------------------------------------
// On sm_100+/sm_103a use packed fma.rn.f32x2 (2 FMA lanes per issue slot).
// On anything else fall back to two scalar fmaf — same numerics (.rn both).
struct fpair { float lo, hi; };

__device__ __forceinline__ fpair ffma2(fpair a, fpair b, fpair c) {
#if defined(__CUDA_ARCH__) && (__CUDA_ARCH__ >= 1000)
    unsigned long long pa, pb, pc, pd;
    asm("mov.b64 %0, {%1, %2};" : "=l"(pa) : "f"(a.lo), "f"(a.hi));
    asm("mov.b64 %0, {%1, %2};" : "=l"(pb) : "f"(b.lo), "f"(b.hi));
    asm("mov.b64 %0, {%1, %2};" : "=l"(pc) : "f"(c.lo), "f"(c.hi));
    asm("fma.rn.f32x2 %0, %1, %2, %3;" : "=l"(pd) : "l"(pa), "l"(pb), "l"(pc));
    fpair d;
    asm("mov.b64 {%0, %1}, %2;" : "=f"(d.lo), "=f"(d.hi) : "l"(pd));
    return d;
#else
    fpair d;
    d.lo = fmaf(a.lo, b.lo, c.lo);
    d.hi = fmaf(a.hi, b.hi, c.hi);
    return d;
#endif
}
__device__ __forceinline__ fpair mkpair(float lo, float hi) {
    fpair p; p.lo = lo; p.hi = hi; return p;
}

// ---------------- Kernel 1: global average pool ---------------------------
// grid = B*CIN blocks, 256 threads; each block reduces one (b,c) plane.
__global__ void gap_kernel(const float* __restrict__ x) {
    int bc = blockIdx.x;
    const float* p = x + (size_t)bc * HW;
    float s = 0.f;
    for (int i = threadIdx.x; i < HW; i += 256) s += p[i];
    __shared__ float red[256];
    red[threadIdx.x] = s;
    __syncthreads();
    for (int off = 128; off > 0; off >>= 1) {
        if (threadIdx.x < off) red[threadIdx.x] += red[threadIdx.x + off];
        __syncthreads();
    }
    if (threadIdx.x == 0) g_v[bc] = red[0] * (1.0f / (float)HW);
}

// ---------------- Kernel 2: routing MLP + softmax -------------------------
// grid = B, 128 threads
__global__ void route_kernel(const float* __restrict__ fc1w,
                             const float* __restrict__ fc1b,
                             const float* __restrict__ fc2w,
                             const float* __restrict__ fc2b) {
    int b = blockIdx.x;
    int t = threadIdx.x;
    __shared__ float v[CIN];
    __shared__ float hd[HIDDEN];
    __shared__ float lg[KEXP];
    v[t] = g_v[b * CIN + t];
    __syncthreads();
    if (t < HIDDEN) {
        float s = fc1b[t];
        #pragma unroll 8
        for (int c = 0; c < CIN; c++) s += v[c] * fc1w[t * CIN + c];
        hd[t] = s > 0.f ? s : 0.f;
    }
    __syncthreads();
    if (t < KEXP) {
        float s = fc2b[t];
        #pragma unroll
        for (int h = 0; h < HIDDEN; h++) s += hd[h] * fc2w[t * HIDDEN + h];
        lg[t] = s;
    }
    __syncthreads();
    if (t == 0) {
        float m = lg[0];
        #pragma unroll
        for (int k = 1; k < KEXP; k++) m = fmaxf(m, lg[k]);
        float e[KEXP];
        float sum = 0.f;
        #pragma unroll
        for (int k = 0; k < KEXP; k++) { e[k] = __expf(lg[k] - m); sum += e[k]; }
        float inv = 1.0f / sum;
        #pragma unroll
        for (int k = 0; k < KEXP; k++) g_alpha[b * KEXP + k] = e[k] * inv;
    }
}

// ---------------- Kernel 3: mix experts -> transposed dyn weights ---------
// grid = (CIN, B), 256 threads. Output layout [b][c][ij][oc].
// bank layout: [k][oc][c][ij] (row-major (8,256,128,3,3))
__global__ void wdyn_kernel(const float* __restrict__ bank) {
    int c = blockIdx.x;
    int b = blockIdx.y;
    int t = threadIdx.x;
    __shared__ float s[COUT * 9];          // 2304 floats, [oc][ij]
    float a[KEXP];
    #pragma unroll
    for (int k = 0; k < KEXP; k++) a[k] = g_alpha[b * KEXP + k];

    // compute: s[oc*9+ij] = sum_k a[k] * bank[((k*COUT+oc)*CIN + c)*9 + ij]
    for (int idx = t; idx < COUT * 9; idx += 256) {
        int oc = idx / 9;
        int ij = idx % 9;
        float acc = 0.f;
        #pragma unroll
        for (int k = 0; k < KEXP; k++)
            acc += a[k] * bank[((size_t)(k * COUT + oc) * CIN + c) * 9 + ij];
        s[idx] = acc;
    }
    __syncthreads();
    // transposed write-out: out[((b*CIN+c)*9+ij)*COUT + oc], oc = tid (coalesced)
    float* outb = g_wdyn + ((size_t)(b * CIN + c) * 9) * COUT;
    #pragma unroll
    for (int ij = 0; ij < 9; ij++)
        outb[ij * COUT + t] = s[t * 9 + ij];   // stride-9 smem read: conflict-free
}

// ---------------- Kernel 4: direct conv (implicit per-sample GEMM) --------
// grid = (49 tiles, COUT/OCB=4, B=32), 128 threads.
// Per thread: 8 oc x 4 px (2 packed pairs), FFMA2 mainloop.
__global__ __launch_bounds__(128) void conv_kernel(const float* __restrict__ x,
                                                   float* __restrict__ out) {
    __shared__ __align__(16) float  sx[KC][10][12];  // halo tile, row stride 12
    __shared__ __align__(16) float2 sw[KC][9][OCB];  // weights duplicated (w,w)

    const int b   = blockIdx.z;
    const int ocb = blockIdx.y * OCB;
    const int tr  = blockIdx.x / 7;
    const int tc  = blockIdx.x % 7;
    const int gr0 = tr * TS;
    const int gc0 = tc * TS;

    const int t   = threadIdx.x;
    const int pxg = t & 15;                  // 16 pixel groups (4 px each)
    const int ocg = t >> 4;                  // 8 oc groups (8 oc each)
    const int r   = pxg >> 1;                // row within tile 0..7
    const int s0  = (pxg & 1) * 4;           // col start 0 or 4
    const int oc0 = ocg * 8;

    fpair acc[8][2];
    #pragma unroll
    for (int o = 0; o < 8; o++) {
        acc[o][0] = mkpair(0.f, 0.f);
        acc[o][1] = mkpair(0.f, 0.f);
    }

    const float* xb = x + (size_t)b * CIN * HW;
    const float* wb = g_wdyn + (size_t)b * CIN * 9 * COUT;

    for (int cc = 0; cc < CIN; cc += KC) {
        __syncthreads();
        // ---- load x halo tile (KC x 10 x 10, zero-padded) ----
        for (int idx = t; idx < KC * 100; idx += 128) {
            int c   = idx / 100;
            int rem = idx - c * 100;
            int lr  = rem / 10;
            int lc  = rem - lr * 10;
            int xr = gr0 + lr - 1;
            int xc = gc0 + lc - 1;
            float v = 0.f;
            if ((unsigned)xr < (unsigned)Hh && (unsigned)xc < (unsigned)Ww)
                v = xb[((size_t)(cc + c) * Hh + xr) * Ww + xc];
            sx[c][lr][lc] = v;
        }
        // ---- load weights, duplicated (coalesced gmem, conflict-free smem) ----
        for (int idx = t; idx < KC * 9 * OCB; idx += 128) {   // 4608 = 36 iters
            int oc = idx & 63;
            int q  = idx >> 6;                // 0..71
            int c  = q / 9;
            int ij = q - c * 9;
            float w = wb[((size_t)(cc + c) * 9 + ij) * COUT + ocb + oc];
            sw[c][ij][oc] = make_float2(w, w);
        }
        __syncthreads();

        // ---- packed FMA mainloop ----
        #pragma unroll 2
        for (int c = 0; c < KC; c++) {
            #pragma unroll
            for (int i = 0; i < 3; i++) {
                const float* xrow = &sx[c][r + i][s0];
                float4 x03 = *reinterpret_cast<const float4*>(xrow);       // aligned
                float2 x45 = *reinterpret_cast<const float2*>(xrow + 4);   // aligned
                fpair p01 = mkpair(x03.x, x03.y);
                fpair p12 = mkpair(x03.y, x03.z);
                fpair p23 = mkpair(x03.z, x03.w);
                fpair p34 = mkpair(x03.w, x45.x);
                fpair p45 = mkpair(x45.x, x45.y);
                const float2* w0 = &sw[c][i * 3 + 0][oc0];
                const float2* w1 = &sw[c][i * 3 + 1][oc0];
                const float2* w2 = &sw[c][i * 3 + 2][oc0];
                #pragma unroll
                for (int o = 0; o < 8; o++) {
                    float2 wv = w0[o];
                    fpair wp = mkpair(wv.x, wv.y);
                    acc[o][0] = ffma2(p01, wp, acc[o][0]);
                    acc[o][1] = ffma2(p23, wp, acc[o][1]);
                }
                #pragma unroll
                for (int o = 0; o < 8; o++) {
                    float2 wv = w1[o];
                    fpair wp = mkpair(wv.x, wv.y);
                    acc[o][0] = ffma2(p12, wp, acc[o][0]);
                    acc[o][1] = ffma2(p34, wp, acc[o][1]);
                }
                #pragma unroll
                for (int o = 0; o < 8; o++) {
                    float2 wv = w2[o];
                    fpair wp = mkpair(wv.x, wv.y);
                    acc[o][0] = ffma2(p23, wp, acc[o][0]);
                    acc[o][1] = ffma2(p45, wp, acc[o][1]);
                }
            }
        }
    }

    // ---- store: 8 oc x 4 px per thread, one float4 per oc ----
    #pragma unroll
    for (int o = 0; o < 8; o++) {
        float4 v = make_float4(acc[o][0].lo, acc[o][0].hi,
                               acc[o][1].lo, acc[o][1].hi);
        size_t oi = (((size_t)b * COUT + ocb + oc0 + o) * Hh + (gr0 + r)) * Ww
                    + gc0 + s0;
        *reinterpret_cast<float4*>(out + oi) = v;
    }
}

// ---------------- launch ---------------------------------------------------
extern "C" void kernel_launch(void* const* d_in, const int* in_sizes, int n_in,
                              void* d_out, int out_size) {
    const float* x    = (const float*)d_in[0];
    const float* bank = (const float*)d_in[1];
    const float* fc1w = (const float*)d_in[2];
    const float* fc1b = (const float*)d_in[3];
    const float* fc2w = (const float*)d_in[4];
    const float* fc2b = (const float*)d_in[5];
    float* out = (float*)d_out;

    gap_kernel<<<BATCH * CIN, 256>>>(x);
    route_kernel<<<BATCH, 128>>>(fc1w, fc1b, fc2w, fc2b);
    wdyn_kernel<<<dim3(CIN, BATCH), 256>>>(bank);
    conv_kernel<<<dim3(49, COUT / OCB, BATCH), 128>>>(x, out);
}

// round 11
// speedup vs baseline: 1.5967x; 1.5967x over previous
#include <cuda_runtime.h>
#include <cuda_bf16.h>

// Problem constants
#define BATCH   32
#define CIN     128
#define COUT    256
#define Hh      56
#define Ww      56
#define KEXP    8
#define HIDDEN  32
#define HW      (Hh * Ww)          // 3136

// Conv tiling
#define KC      8                  // cin chunk
#define OCB     128                // oc per block (64 consecutive-oc float2 pairs)
#define TS      8                  // 8x8 spatial tile

typedef unsigned long long ull;

// ---------------- scratch (static device globals; no runtime alloc) -------
__device__ float g_v[BATCH * CIN];                    // GAP result
__device__ float g_alpha[BATCH * KEXP];               // routing weights
// Dynamic weights, TRANSPOSED layout: [b][c][ij][oc]  (oc fastest)
__device__ float g_wdyn[BATCH * CIN * 9 * COUT];      // 37.7 MB

// ---------------- packed f32x2 helpers (operands stay packed in u64) ------
__device__ __forceinline__ ull ffma2(ull a, ull b, ull c) {
#if defined(__CUDA_ARCH__) && (__CUDA_ARCH__ >= 1000)
    ull d;
    asm("fma.rn.f32x2 %0, %1, %2, %3;" : "=l"(d) : "l"(a), "l"(b), "l"(c));
    return d;
#else
    float alo, ahi, blo, bhi, clo, chi;
    asm("mov.b64 {%0, %1}, %2;" : "=f"(alo), "=f"(ahi) : "l"(a));
    asm("mov.b64 {%0, %1}, %2;" : "=f"(blo), "=f"(bhi) : "l"(b));
    asm("mov.b64 {%0, %1}, %2;" : "=f"(clo), "=f"(chi) : "l"(c));
    float dlo = fmaf(alo, blo, clo);
    float dhi = fmaf(ahi, bhi, chi);
    ull d;
    asm("mov.b64 %0, {%1, %2};" : "=l"(d) : "f"(dlo), "f"(dhi));
    return d;
#endif
}
__device__ __forceinline__ ull packdup(float v) {          // (v, v)
    ull d;
    asm("mov.b64 %0, {%1, %2};" : "=l"(d) : "f"(v), "f"(v));
    return d;
}
__device__ __forceinline__ void unpack2(ull p, float& lo, float& hi) {
    asm("mov.b64 {%0, %1}, %2;" : "=f"(lo), "=f"(hi) : "l"(p));
}

// ---------------- Kernel 1: global average pool ---------------------------
__global__ void gap_kernel(const float* __restrict__ x) {
    int bc = blockIdx.x;
    const float* p = x + (size_t)bc * HW;
    float s = 0.f;
    for (int i = threadIdx.x; i < HW; i += 256) s += p[i];
    __shared__ float red[256];
    red[threadIdx.x] = s;
    __syncthreads();
    for (int off = 128; off > 0; off >>= 1) {
        if (threadIdx.x < off) red[threadIdx.x] += red[threadIdx.x + off];
        __syncthreads();
    }
    if (threadIdx.x == 0) g_v[bc] = red[0] * (1.0f / (float)HW);
}

// ---------------- Kernel 2: routing MLP + softmax -------------------------
__global__ void route_kernel(const float* __restrict__ fc1w,
                             const float* __restrict__ fc1b,
                             const float* __restrict__ fc2w,
                             const float* __restrict__ fc2b) {
    int b = blockIdx.x;
    int t = threadIdx.x;
    __shared__ float v[CIN];
    __shared__ float hd[HIDDEN];
    __shared__ float lg[KEXP];
    v[t] = g_v[b * CIN + t];
    __syncthreads();
    if (t < HIDDEN) {
        float s = fc1b[t];
        #pragma unroll 8
        for (int c = 0; c < CIN; c++) s += v[c] * fc1w[t * CIN + c];
        hd[t] = s > 0.f ? s : 0.f;
    }
    __syncthreads();
    if (t < KEXP) {
        float s = fc2b[t];
        #pragma unroll
        for (int h = 0; h < HIDDEN; h++) s += hd[h] * fc2w[t * HIDDEN + h];
        lg[t] = s;
    }
    __syncthreads();
    if (t == 0) {
        float m = lg[0];
        #pragma unroll
        for (int k = 1; k < KEXP; k++) m = fmaxf(m, lg[k]);
        float e[KEXP];
        float sum = 0.f;
        #pragma unroll
        for (int k = 0; k < KEXP; k++) { e[k] = __expf(lg[k] - m); sum += e[k]; }
        float inv = 1.0f / sum;
        #pragma unroll
        for (int k = 0; k < KEXP; k++) g_alpha[b * KEXP + k] = e[k] * inv;
    }
}

// ---------------- Kernel 3: mix experts -> transposed dyn weights ---------
// grid = (CIN, B), 256 threads. Output layout [b][c][ij][oc] (oc fastest).
__global__ void wdyn_kernel(const float* __restrict__ bank) {
    int c = blockIdx.x;
    int b = blockIdx.y;
    int t = threadIdx.x;
    __shared__ float s[COUT * 9];
    float a[KEXP];
    #pragma unroll
    for (int k = 0; k < KEXP; k++) a[k] = g_alpha[b * KEXP + k];

    for (int idx = t; idx < COUT * 9; idx += 256) {
        int oc = idx / 9;
        int ij = idx % 9;
        float acc = 0.f;
        #pragma unroll
        for (int k = 0; k < KEXP; k++)
            acc += a[k] * bank[((size_t)(k * COUT + oc) * CIN + c) * 9 + ij];
        s[idx] = acc;
    }
    __syncthreads();
    float* outb = g_wdyn + ((size_t)(b * CIN + c) * 9) * COUT;
    #pragma unroll
    for (int ij = 0; ij < 9; ij++)
        outb[ij * COUT + t] = s[t * 9 + ij];
}

// ---------------- Kernel 4: direct conv, oc-packed f32x2 ------------------
// grid = (49 tiles, COUT/OCB=2, B=32), 128 threads.
// Thread t: row r = t>>4 (full 8-px row), oc-group ocg = t&15.
// Per thread: 4 oc-pairs (8 oc) x 8 px, acc kept packed in u64.
__global__ __launch_bounds__(128) void conv_kernel(const float* __restrict__ x,
                                                   float* __restrict__ out) {
    __shared__ __align__(16) float  sx[KC][10][12];        // halo, row stride 12
    __shared__ __align__(16) float2 sw[KC][9][OCB / 2];    // consecutive-oc pairs

    const int b   = blockIdx.z;
    const int ocb = blockIdx.y * OCB;
    const int tr  = blockIdx.x / 7;
    const int tc  = blockIdx.x % 7;
    const int gr0 = tr * TS;
    const int gc0 = tc * TS;

    const int t   = threadIdx.x;
    const int r   = t >> 4;                  // 0..7
    const int ocg = t & 15;                  // 0..15

    ull acc[4][8];
    #pragma unroll
    for (int p = 0; p < 4; p++)
        #pragma unroll
        for (int s = 0; s < 8; s++) acc[p][s] = 0ull;

    const float* xb = x + (size_t)b * CIN * HW;
    const float* wb = g_wdyn + (size_t)b * CIN * 9 * COUT;

    #pragma unroll 1
    for (int cc = 0; cc < CIN; cc += KC) {
        __syncthreads();
        // ---- x halo tile (KC x 10 x 10, zero-padded) ----
        for (int idx = t; idx < KC * 100; idx += 128) {
            int c   = idx / 100;
            int rem = idx - c * 100;
            int lr  = rem / 10;
            int lc  = rem - lr * 10;
            int xr = gr0 + lr - 1;
            int xc = gc0 + lc - 1;
            float v = 0.f;
            if ((unsigned)xr < (unsigned)Hh && (unsigned)xc < (unsigned)Ww)
                v = xb[((size_t)(cc + c) * Hh + xr) * Ww + xc];
            sx[c][lr][lc] = v;
        }
        // ---- weights: straight float4 copy, no duplication ----
        // KC*9*(OCB/4) = 2304 float4 -> 18 per thread, all coalesced
        for (int idx = t; idx < KC * 9 * (OCB / 4); idx += 128) {
            int c   = idx / (9 * 32);
            int rem = idx - c * (9 * 32);
            int ij  = rem >> 5;
            int q   = rem & 31;
            const float4* src = reinterpret_cast<const float4*>(
                wb + ((size_t)(cc + c) * 9 + ij) * COUT + ocb) + q;
            reinterpret_cast<float4*>(&sw[c][ij][0])[q] = *src;
        }
        __syncthreads();

        // ---- packed mainloop ----
        #pragma unroll 2
        for (int c = 0; c < KC; c++) {
            #pragma unroll
            for (int i = 0; i < 3; i++) {
                const float* xrow = &sx[c][r + i][0];
                float4 xa = *reinterpret_cast<const float4*>(xrow);
                float4 xbq = *reinterpret_cast<const float4*>(xrow + 4);
                float2 xcq = *reinterpret_cast<const float2*>(xrow + 8);
                ull xp[10];
                xp[0] = packdup(xa.x);  xp[1] = packdup(xa.y);
                xp[2] = packdup(xa.z);  xp[3] = packdup(xa.w);
                xp[4] = packdup(xbq.x); xp[5] = packdup(xbq.y);
                xp[6] = packdup(xbq.z); xp[7] = packdup(xbq.w);
                xp[8] = packdup(xcq.x); xp[9] = packdup(xcq.y);
                #pragma unroll
                for (int j = 0; j < 3; j++) {
                    #pragma unroll
                    for (int p = 0; p < 4; p++) {
                        // 16 consecutive 8B words across ocg: conflict-free
                        ull w = *reinterpret_cast<const ull*>(
                            &sw[c][i * 3 + j][p * 16 + ocg]);
                        #pragma unroll
                        for (int s = 0; s < 8; s++)
                            acc[p][s] = ffma2(xp[s + j], w, acc[p][s]);
                    }
                }
            }
        }
    }

    // ---- epilogue: 4 oc-pairs x 8 px ----
    #pragma unroll
    for (int p = 0; p < 4; p++) {
        float lo[8], hi[8];
        #pragma unroll
        for (int s = 0; s < 8; s++) unpack2(acc[p][s], lo[s], hi[s]);
        int oc = ocb + (p * 16 + ocg) * 2;
        size_t base0 = (((size_t)b * COUT + oc) * Hh + (gr0 + r)) * Ww + gc0;
        size_t base1 = base0 + (size_t)HW;
        *reinterpret_cast<float4*>(out + base0)     = make_float4(lo[0], lo[1], lo[2], lo[3]);
        *reinterpret_cast<float4*>(out + base0 + 4) = make_float4(lo[4], lo[5], lo[6], lo[7]);
        *reinterpret_cast<float4*>(out + base1)     = make_float4(hi[0], hi[1], hi[2], hi[3]);
        *reinterpret_cast<float4*>(out + base1 + 4) = make_float4(hi[4], hi[5], hi[6], hi[7]);
    }
}

// ---------------- launch ---------------------------------------------------
extern "C" void kernel_launch(void* const* d_in, const int* in_sizes, int n_in,
                              void* d_out, int out_size) {
    const float* x    = (const float*)d_in[0];
    const float* bank = (const float*)d_in[1];
    const float* fc1w = (const float*)d_in[2];
    const float* fc1b = (const float*)d_in[3];
    const float* fc2w = (const float*)d_in[4];
    const float* fc2b = (const float*)d_in[5];
    float* out = (float*)d_out;

    gap_kernel<<<BATCH * CIN, 256>>>(x);
    route_kernel<<<BATCH, 128>>>(fc1w, fc1b, fc2w, fc2b);
    wdyn_kernel<<<dim3(CIN, BATCH), 256>>>(bank);
    conv_kernel<<<dim3(49, COUT / OCB, BATCH), 128>>>(x, out);
}

// round 16
// speedup vs baseline: 2.6004x; 1.6286x over previous
#include <cuda_runtime.h>
#include <cuda_bf16.h>
#include <cstdint>

// Problem constants
#define BATCH   32
#define CIN     128
#define COUT    256
#define Hh      56
#define Ww      56
#define KEXP    8
#define HIDDEN  32
#define HW      (Hh * Ww)          // 3136

// ---------------- scratch (static device globals; no runtime alloc) -------
__device__ float g_v[BATCH * CIN];                    // GAP result
__device__ float g_alpha[BATCH * KEXP];               // routing weights
// split weights, layout [b][ij][oc][c] bf16
__device__ __nv_bfloat16 g_wh[BATCH * 9 * COUT * CIN];
__device__ __nv_bfloat16 g_wl[BATCH * 9 * COUT * CIN];
// split input, channels-last [b][h*w][c] bf16
__device__ __nv_bfloat16 g_xh[BATCH * HW * CIN];
__device__ __nv_bfloat16 g_xl[BATCH * HW * CIN];

__device__ __forceinline__ uint32_t smem_u32(const void* p) {
    uint32_t a;
    asm("{ .reg .u64 t; cvta.to.shared.u64 t, %1; cvt.u32.u64 %0, t; }"
        : "=r"(a) : "l"(p));
    return a;
}

#define LDSM4(r, a) \
    asm volatile("ldmatrix.sync.aligned.m8n8.x4.shared.b16 {%0,%1,%2,%3}, [%4];" \
                 : "=r"((r)[0]), "=r"((r)[1]), "=r"((r)[2]), "=r"((r)[3]) : "r"(a))
#define LDSM2(r, a) \
    asm volatile("ldmatrix.sync.aligned.m8n8.x2.shared.b16 {%0,%1}, [%2];" \
                 : "=r"((r)[0]), "=r"((r)[1]) : "r"(a))
#define MMA16816(c, a, b) \
    asm volatile("mma.sync.aligned.m16n8k16.row.col.f32.bf16.bf16.f32 " \
                 "{%0,%1,%2,%3}, {%4,%5,%6,%7}, {%8,%9}, {%0,%1,%2,%3};" \
                 : "+f"((c)[0]), "+f"((c)[1]), "+f"((c)[2]), "+f"((c)[3]) \
                 : "r"((a)[0]), "r"((a)[1]), "r"((a)[2]), "r"((a)[3]), \
                   "r"((b)[0]), "r"((b)[1]))

// ---------------- Kernel 1: global average pool ---------------------------
__global__ void gap_kernel(const float* __restrict__ x) {
    int bc = blockIdx.x;
    const float* p = x + (size_t)bc * HW;
    float s = 0.f;
    for (int i = threadIdx.x; i < HW; i += 256) s += p[i];
    __shared__ float red[256];
    red[threadIdx.x] = s;
    __syncthreads();
    for (int off = 128; off > 0; off >>= 1) {
        if (threadIdx.x < off) red[threadIdx.x] += red[threadIdx.x + off];
        __syncthreads();
    }
    if (threadIdx.x == 0) g_v[bc] = red[0] * (1.0f / (float)HW);
}

// ---------------- Kernel 2: routing MLP + softmax -------------------------
__global__ void route_kernel(const float* __restrict__ fc1w,
                             const float* __restrict__ fc1b,
                             const float* __restrict__ fc2w,
                             const float* __restrict__ fc2b) {
    int b = blockIdx.x;
    int t = threadIdx.x;
    __shared__ float v[CIN];
    __shared__ float hd[HIDDEN];
    __shared__ float lg[KEXP];
    v[t] = g_v[b * CIN + t];
    __syncthreads();
    if (t < HIDDEN) {
        float s = fc1b[t];
        #pragma unroll 8
        for (int c = 0; c < CIN; c++) s += v[c] * fc1w[t * CIN + c];
        hd[t] = s > 0.f ? s : 0.f;
    }
    __syncthreads();
    if (t < KEXP) {
        float s = fc2b[t];
        #pragma unroll
        for (int h = 0; h < HIDDEN; h++) s += hd[h] * fc2w[t * HIDDEN + h];
        lg[t] = s;
    }
    __syncthreads();
    if (t == 0) {
        float m = lg[0];
        #pragma unroll
        for (int k = 1; k < KEXP; k++) m = fmaxf(m, lg[k]);
        float e[KEXP];
        float sum = 0.f;
        #pragma unroll
        for (int k = 0; k < KEXP; k++) { e[k] = __expf(lg[k] - m); sum += e[k]; }
        float inv = 1.0f / sum;
        #pragma unroll
        for (int k = 0; k < KEXP; k++) g_alpha[b * KEXP + k] = e[k] * inv;
    }
}

// ---------------- Kernel 3: x -> channels-last bf16 hi/lo -----------------
__global__ void xsplit_kernel(const float* __restrict__ x) {
    __shared__ float s[CIN][33];
    int px0 = blockIdx.x * 32;
    int b   = blockIdx.y;
    int t   = threadIdx.x;
    const float* xb = x + (size_t)b * CIN * HW;
    #pragma unroll
    for (int i = 0; i < 16; i++) {
        int idx = i * 256 + t;
        int c = idx >> 5;
        int p = idx & 31;
        s[c][p] = xb[(size_t)c * HW + px0 + p];
    }
    __syncthreads();
    __nv_bfloat16* oh = g_xh + ((size_t)b * HW + px0) * CIN;
    __nv_bfloat16* ol = g_xl + ((size_t)b * HW + px0) * CIN;
    #pragma unroll
    for (int i = 0; i < 16; i++) {
        int idx = i * 256 + t;
        int p = idx >> 7;
        int c = idx & 127;
        float v = s[c][p];
        __nv_bfloat16 hi = __float2bfloat16(v);
        __nv_bfloat16 lo = __float2bfloat16(v - __bfloat162float(hi));
        oh[(size_t)p * CIN + c] = hi;
        ol[(size_t)p * CIN + c] = lo;
    }
}

// ---------------- Kernel 4: expert-mix weights -> bf16 hi/lo --------------
// layout out: [b][ij][oc][c]; bank layout [k][oc][c][ij]
__global__ void wsplit_kernel(const float* __restrict__ bank) {
    int ocb = blockIdx.x * 32;
    int b   = blockIdx.y;
    int t   = threadIdx.x;
    float a[KEXP];
    #pragma unroll
    for (int k = 0; k < KEXP; k++) a[k] = g_alpha[b * KEXP + k];

    #pragma unroll 1
    for (int i = 0; i < 16; i++) {
        int id = i * 256 + t;
        int oc = ocb + (id >> 7);
        int c  = id & 127;
        float acc[9];
        #pragma unroll
        for (int ij = 0; ij < 9; ij++) acc[ij] = 0.f;
        #pragma unroll
        for (int k = 0; k < KEXP; k++) {
            const float* p = bank + ((size_t)(k * COUT + oc) * CIN + c) * 9;
            float av = a[k];
            #pragma unroll
            for (int ij = 0; ij < 9; ij++) acc[ij] += av * p[ij];
        }
        #pragma unroll
        for (int ij = 0; ij < 9; ij++) {
            float v = acc[ij];
            __nv_bfloat16 hi = __float2bfloat16(v);
            __nv_bfloat16 lo = __float2bfloat16(v - __bfloat162float(hi));
            size_t o = (((size_t)b * 9 + ij) * COUT + oc) * CIN + c;
            g_wh[o] = hi;
            g_wl[o] = lo;
        }
    }
}

// ---------------- Kernel 5: mma.sync implicit-GEMM conv -------------------
// grid (28 px tiles, 2 ocb, 32 b), 256 threads (8 warps, 4M x 2N).
// CTA tile: 128 oc x 112 flat px. Warp: 32 oc x 56 px (2 m16 x 7 n8).
// K: 18 chunks = 9 taps x 2 c-halves(64). 3 passes: Ah*Bh + Al*Bh + Ah*Bl.
#define NPX     112
#define OFF_AH  0
#define OFF_AL  16384
#define OFF_BH  32768
#define OFF_BL  (32768 + 14336)
#define SMEM_USED (OFF_BL + 14336)      // 61440
#define SMEM_ALLOC (SMEM_USED + 1024)

__global__ __launch_bounds__(256)
void conv_mma_kernel(float* __restrict__ out) {
    extern __shared__ char smem_raw[];
    uint32_t sb_raw = smem_u32(smem_raw);
    uint32_t sb = (sb_raw + 1023u) & ~1023u;
    char* smem = smem_raw + (sb - sb_raw);

    const int t   = threadIdx.x;
    const int wid = t >> 5;
    const int l   = t & 31;
    const int b   = blockIdx.z;
    const int ocb = blockIdx.y;              // 0 or 1 (128 oc each)
    const int pxb = blockIdx.x * NPX;        // flat pixel base

    const int wm = wid & 3;                  // 4 M-groups of 32 oc
    const int wn = wid >> 2;                 // 2 N-groups of 56 px
    const uint32_t sw = (uint32_t)(l & 7) * 16;          // swizzle XOR per lane
    const uint32_t aRowOff = (uint32_t)(wm * 32 + (l & 15)) * 128;
    const uint32_t aHi = (uint32_t)(l >> 4) * 16;
    const uint32_t bRowOff = (uint32_t)(wn * 56 + (l & 7)) * 128;
    const uint32_t bHi = (uint32_t)((l >> 3) & 1) * 16;

    float acc[2][7][4];
    #pragma unroll
    for (int mt = 0; mt < 2; mt++)
        #pragma unroll
        for (int nt = 0; nt < 7; nt++)
            #pragma unroll
            for (int k = 0; k < 4; k++) acc[mt][nt][k] = 0.f;

    #pragma unroll 1
    for (int chunk = 0; chunk < 18; chunk++) {
        int ij = chunk >> 1;
        int ch = chunk & 1;
        int di = ij / 3 - 1;
        int dj = ij % 3 - 1;

        __syncthreads();
        // ---- fill A tiles: [hi/lo][128 oc][64 c], 2048 uint4 ----
        #pragma unroll
        for (int i = 0; i < 8; i++) {
            int idx = i * 256 + t;
            int hl  = idx >> 10;
            int oc  = (idx >> 3) & 127;
            int q   = idx & 7;
            const __nv_bfloat16* src =
                (hl ? g_wl : g_wh) +
                ((((size_t)b * 9 + ij) * COUT + ocb * 128 + oc) * CIN + ch * 64
                 + q * 8);
            uint4 v = *reinterpret_cast<const uint4*>(src);
            uint32_t off = (hl ? OFF_AL : OFF_AH) + (uint32_t)oc * 128
                         + (((uint32_t)q * 16) ^ ((uint32_t)(oc & 7) * 16));
            *reinterpret_cast<uint4*>(smem + off) = v;
        }
        // ---- fill B tiles (im2col): [hi/lo][112 px][64 c], 1792 uint4 ----
        #pragma unroll
        for (int i = 0; i < 7; i++) {
            int idx = i * 256 + t;
            int hl  = idx >> 10;          // 0..895 hi, 896.. lo
            int rem = idx & 1023;
            if (hl) rem = idx - 1024;
            // simpler split: idx<896 -> hi, else lo
            hl = (idx >= 896) ? 1 : 0;
            rem = hl ? idx - 896 : idx;
            int p  = rem >> 3;
            int q  = rem & 7;
            int pg = pxb + p;
            int hh = pg / Ww + di;
            int ww = pg % Ww + dj;
            uint4 v = make_uint4(0u, 0u, 0u, 0u);
            if ((unsigned)hh < (unsigned)Hh && (unsigned)ww < (unsigned)Ww) {
                const __nv_bfloat16* src =
                    (hl ? g_xl : g_xh) +
                    (((size_t)b * HW + hh * Ww + ww) * CIN + ch * 64 + q * 8);
                v = *reinterpret_cast<const uint4*>(src);
            }
            uint32_t off = (hl ? OFF_BL : OFF_BH) + (uint32_t)p * 128
                         + (((uint32_t)q * 16) ^ ((uint32_t)(p & 7) * 16));
            *reinterpret_cast<uint4*>(smem + off) = v;
        }
        __syncthreads();

        // ---- compute: 4 k16 steps x 3 passes ----
        #pragma unroll
        for (int ks = 0; ks < 4; ks++) {
            uint32_t colA = ((uint32_t)ks * 32 + aHi) ^ sw;
            uint32_t colB = ((uint32_t)ks * 32 + bHi) ^ sw;
            uint32_t ah[2][4], bhf[7][2];
            #pragma unroll
            for (int mt = 0; mt < 2; mt++)
                LDSM4(ah[mt], sb + OFF_AH + aRowOff + (uint32_t)mt * 2048 + colA);
            #pragma unroll
            for (int nt = 0; nt < 7; nt++)
                LDSM2(bhf[nt], sb + OFF_BH + bRowOff + (uint32_t)nt * 1024 + colB);
            // pass 0: Ah * Bh
            #pragma unroll
            for (int mt = 0; mt < 2; mt++)
                #pragma unroll
                for (int nt = 0; nt < 7; nt++)
                    MMA16816(acc[mt][nt], ah[mt], bhf[nt]);
            // pass 1: Al * Bh
            #pragma unroll
            for (int mt = 0; mt < 2; mt++) {
                uint32_t alf[4];
                LDSM4(alf, sb + OFF_AL + aRowOff + (uint32_t)mt * 2048 + colA);
                #pragma unroll
                for (int nt = 0; nt < 7; nt++)
                    MMA16816(acc[mt][nt], alf, bhf[nt]);
            }
            // pass 2: Ah * Bl
            #pragma unroll
            for (int nt = 0; nt < 7; nt++) {
                uint32_t blf[2];
                LDSM2(blf, sb + OFF_BL + bRowOff + (uint32_t)nt * 1024 + colB);
                #pragma unroll
                for (int mt = 0; mt < 2; mt++)
                    MMA16816(acc[mt][nt], ah[mt], blf);
            }
        }
    }

    // ---- epilogue: fragment -> gmem (output px are flat-contiguous) ------
    const int g  = l >> 2;
    const int tq = l & 3;
    #pragma unroll
    for (int mt = 0; mt < 2; mt++) {
        int oc = ocb * 128 + wm * 32 + mt * 16 + g;
        #pragma unroll
        for (int nt = 0; nt < 7; nt++) {
            int px = pxb + wn * 56 + nt * 8 + tq * 2;
            float* o0 = out + ((size_t)b * COUT + oc) * HW + px;
            float* o1 = out + ((size_t)b * COUT + oc + 8) * HW + px;
            *reinterpret_cast<float2*>(o0) =
                make_float2(acc[mt][nt][0], acc[mt][nt][1]);
            *reinterpret_cast<float2*>(o1) =
                make_float2(acc[mt][nt][2], acc[mt][nt][3]);
        }
    }
}

// ---------------- launch ---------------------------------------------------
extern "C" void kernel_launch(void* const* d_in, const int* in_sizes, int n_in,
                              void* d_out, int out_size) {
    const float* x    = (const float*)d_in[0];
    const float* bank = (const float*)d_in[1];
    const float* fc1w = (const float*)d_in[2];
    const float* fc1b = (const float*)d_in[3];
    const float* fc2w = (const float*)d_in[4];
    const float* fc2b = (const float*)d_in[5];
    float* out = (float*)d_out;

    cudaFuncSetAttribute(conv_mma_kernel,
                         cudaFuncAttributeMaxDynamicSharedMemorySize,
                         SMEM_ALLOC);

    gap_kernel<<<BATCH * CIN, 256>>>(x);
    route_kernel<<<BATCH, 128>>>(fc1w, fc1b, fc2w, fc2b);
    xsplit_kernel<<<dim3(HW / 32, BATCH), 256>>>(x);
    wsplit_kernel<<<dim3(COUT / 32, BATCH), 256>>>(bank);
    conv_mma_kernel<<<dim3(HW / NPX, 2, BATCH), 256, SMEM_ALLOC>>>(out);
}